// round 1
// baseline (speedup 1.0000x reference)
#include <cuda_runtime.h>

#define S_LEN  2048
#define DMODEL 1024
#define NHEAD  16
#define DHEAD  64
#define BATCH  2

// Scratch (static device globals — no runtime allocation).
__device__ float g_q[BATCH * NHEAD * S_LEN * DHEAD];
__device__ float g_k[BATCH * NHEAD * S_LEN * DHEAD];
__device__ float g_v[BATCH * NHEAD * S_LEN * DHEAD];
__device__ float g_attn[BATCH * S_LEN * DMODEL];

// ---- packed f32x2 helpers (FFMA2 path: 2x fp32 FMA throughput on sm_103a) ----
__device__ __forceinline__ unsigned long long pack2(float lo, float hi) {
    unsigned long long r;
    asm("mov.b64 %0, {%1, %2};" : "=l"(r) : "f"(lo), "f"(hi));
    return r;
}
__device__ __forceinline__ float2 unpack2(unsigned long long v) {
    float2 f;
    asm("mov.b64 {%0, %1}, %2;" : "=f"(f.x), "=f"(f.y) : "l"(v));
    return f;
}
__device__ __forceinline__ unsigned long long fma2(unsigned long long a,
                                                   unsigned long long b,
                                                   unsigned long long c) {
    unsigned long long d;
    asm("fma.rn.f32x2 %0, %1, %2, %3;" : "=l"(d) : "l"(a), "l"(b), "l"(c));
    return d;
}
__device__ __forceinline__ unsigned long long mul2(unsigned long long a,
                                                   unsigned long long b) {
    unsigned long long d;
    asm("mul.rn.f32x2 %0, %1, %2;" : "=l"(d) : "l"(a), "l"(b));
    return d;
}

// ============================================================================
// SGEMM: 128x128x8 tile, 256 threads, 8x8 per thread, f32x2 inner product.
// MODE 0: C = A@B + bias, scatter into g_q/g_k/g_v as [B,H,S,dh]
// MODE 2: C = g_attn@B + bias, plain row-major store to C
// ============================================================================
template <int MODE>
__global__ __launch_bounds__(256) void sgemm_kernel(
    const float* __restrict__ A, const float* __restrict__ B,
    const float* __restrict__ bias, float* __restrict__ C,
    int M, int N, int K)
{
    __shared__ float As[8][132];   // A^T tile, padded
    __shared__ float Bs[8][128];

    const float* Abase = (MODE == 2) ? (const float*)g_attn : A;

    int tid = threadIdx.x;
    int bm = blockIdx.y * 128, bn = blockIdx.x * 128;
    int arow = tid >> 1, acol = (tid & 1) * 4;
    int brow = tid >> 5, bcol = (tid & 31) * 4;
    int ty = tid >> 4, tx = tid & 15;

    unsigned long long acc[8][4];
#pragma unroll
    for (int i = 0; i < 8; i++)
#pragma unroll
        for (int j = 0; j < 4; j++) acc[i][j] = 0ULL;

    const float* Ap = Abase + (size_t)(bm + arow) * K + acol;
    const float* Bp = B + bn + bcol;

    for (int k0 = 0; k0 < K; k0 += 8) {
        float4 av = *(const float4*)(Ap + k0);
        float4 bv = *(const float4*)(Bp + (size_t)(k0 + brow) * N);
        As[acol + 0][arow] = av.x;
        As[acol + 1][arow] = av.y;
        As[acol + 2][arow] = av.z;
        As[acol + 3][arow] = av.w;
        *(float4*)&Bs[brow][bcol] = bv;
        __syncthreads();

#pragma unroll
        for (int kk = 0; kk < 8; kk++) {
            float4 a0 = *(const float4*)&As[kk][ty * 8];
            float4 a1 = *(const float4*)&As[kk][ty * 8 + 4];
            ulonglong2 b01 = *(const ulonglong2*)&Bs[kk][tx * 8];
            ulonglong2 b23 = *(const ulonglong2*)&Bs[kk][tx * 8 + 4];
            float ra[8] = {a0.x, a0.y, a0.z, a0.w, a1.x, a1.y, a1.z, a1.w};
#pragma unroll
            for (int i = 0; i < 8; i++) {
                unsigned long long aa = pack2(ra[i], ra[i]);
                acc[i][0] = fma2(aa, b01.x, acc[i][0]);
                acc[i][1] = fma2(aa, b01.y, acc[i][1]);
                acc[i][2] = fma2(aa, b23.x, acc[i][2]);
                acc[i][3] = fma2(aa, b23.y, acc[i][3]);
            }
        }
        __syncthreads();
    }

    float bias_v[8];
#pragma unroll
    for (int jj = 0; jj < 8; jj++) bias_v[jj] = bias[bn + tx * 8 + jj];

    if (MODE == 2) {
#pragma unroll
        for (int i = 0; i < 8; i++) {
            int gm = bm + ty * 8 + i;
            float2 p0 = unpack2(acc[i][0]), p1 = unpack2(acc[i][1]);
            float2 p2 = unpack2(acc[i][2]), p3 = unpack2(acc[i][3]);
            float4 o0 = {p0.x + bias_v[0], p0.y + bias_v[1],
                         p1.x + bias_v[2], p1.y + bias_v[3]};
            float4 o1 = {p2.x + bias_v[4], p2.y + bias_v[5],
                         p3.x + bias_v[6], p3.y + bias_v[7]};
            *(float4*)&C[(size_t)gm * N + bn + tx * 8] = o0;
            *(float4*)&C[(size_t)gm * N + bn + tx * 8 + 4] = o1;
        }
    } else {
        // Scatter: columns [0,1024)->Q, [1024,2048)->K, [2048,3072)->V;
        // layout [B,H,S,dh]. Tile (128 cols) never crosses a section boundary.
        float* dst = (bn < 1024) ? g_q : (bn < 2048 ? g_k : g_v);
        int gn0 = bn + tx * 8;
        int w0 = gn0 & 1023;
        int h0 = w0 >> 6, d0 = w0 & 63;
        int w1 = (gn0 + 4) & 1023;
        int h1 = w1 >> 6, d1 = w1 & 63;
#pragma unroll
        for (int i = 0; i < 8; i++) {
            int gm = bm + ty * 8 + i;
            int b = gm >> 11, s = gm & 2047;
            float2 p0 = unpack2(acc[i][0]), p1 = unpack2(acc[i][1]);
            float2 p2 = unpack2(acc[i][2]), p3 = unpack2(acc[i][3]);
            float4 o0 = {p0.x + bias_v[0], p0.y + bias_v[1],
                         p1.x + bias_v[2], p1.y + bias_v[3]};
            float4 o1 = {p2.x + bias_v[4], p2.y + bias_v[5],
                         p3.x + bias_v[6], p3.y + bias_v[7]};
            size_t base0 = (((size_t)b * NHEAD + h0) * S_LEN + s) * DHEAD + d0;
            size_t base1 = (((size_t)b * NHEAD + h1) * S_LEN + s) * DHEAD + d1;
            *(float4*)&dst[base0] = o0;
            *(float4*)&dst[base1] = o1;
        }
    }
}

// ============================================================================
// Flash attention: one block per (64-query tile, head, batch).
// 256 threads = 16x16; each thread owns a 4x4 micro-tile.
// Online softmax with the multiplicative mask:
//   t = (q.k)*scale*m + (m-1)*10000  (q prescaled by 1/8)
// ============================================================================
__global__ __launch_bounds__(256) void flash_kernel(const float* __restrict__ mask)
{
    extern __shared__ float sm[];
    float* Qs = sm;                 // [64][68]  [q][d]
    float* Ks = sm + 64 * 68;       // [64][68]  [d][k]  (transposed)
    float* Vs = sm + 2 * 64 * 68;   // [64][68]  [k][d]
    float* Ps = sm + 3 * 64 * 68;   // [64][68]  [q][k]

    int tid = threadIdx.x;
    int tx = tid & 15, ty = tid >> 4;
    int q0 = blockIdx.x * 64;
    int h = blockIdx.y, b = blockIdx.z;

    const float* Qg = g_q + (((size_t)b * NHEAD + h) * S_LEN + q0) * DHEAD;
    const float* Kg = g_k + ((size_t)b * NHEAD + h) * S_LEN * DHEAD;
    const float* Vg = g_v + ((size_t)b * NHEAD + h) * S_LEN * DHEAD;
    const float* Mg = mask + (size_t)b * S_LEN * S_LEN + (size_t)q0 * S_LEN;

    // Load Q tile, prescaled by dh^-0.5 = 0.125
#pragma unroll
    for (int t = 0; t < 4; t++) {
        int fidx = tid + t * 256;
        int row = fidx >> 4, c4 = (fidx & 15) * 4;
        float4 v = *(const float4*)(Qg + row * 64 + c4);
        v.x *= 0.125f; v.y *= 0.125f; v.z *= 0.125f; v.w *= 0.125f;
        *(float4*)&Qs[row * 68 + c4] = v;
    }

    unsigned long long acc[4][2];
    float m_i[4], l_i[4];
#pragma unroll
    for (int i = 0; i < 4; i++) {
        acc[i][0] = 0ULL; acc[i][1] = 0ULL;
        m_i[i] = -1e30f; l_i[i] = 0.0f;
    }

    for (int kt = 0; kt < S_LEN / 64; kt++) {
        __syncthreads();   // previous PV done before overwriting K/V
        // Load K (transposed to [d][k]) and V ([k][d])
#pragma unroll
        for (int t = 0; t < 4; t++) {
            int fidx = tid + t * 256;
            int row = fidx >> 4, c4 = (fidx & 15) * 4;
            float4 kv = *(const float4*)(Kg + (size_t)(kt * 64 + row) * 64 + c4);
            Ks[(c4 + 0) * 68 + row] = kv.x;
            Ks[(c4 + 1) * 68 + row] = kv.y;
            Ks[(c4 + 2) * 68 + row] = kv.z;
            Ks[(c4 + 3) * 68 + row] = kv.w;
            float4 vv = *(const float4*)(Vg + (size_t)(kt * 64 + row) * 64 + c4);
            *(float4*)&Vs[row * 68 + c4] = vv;
        }
        __syncthreads();

        // S = Q @ K^T  (contraction over d)
        unsigned long long s2[4][2];
#pragma unroll
        for (int i = 0; i < 4; i++) { s2[i][0] = 0ULL; s2[i][1] = 0ULL; }
#pragma unroll 16
        for (int d = 0; d < 64; d++) {
            ulonglong2 kk2 = *(const ulonglong2*)&Ks[d * 68 + tx * 4];
#pragma unroll
            for (int i = 0; i < 4; i++) {
                float qv = Qs[(ty * 4 + i) * 68 + d];
                unsigned long long aa = pack2(qv, qv);
                s2[i][0] = fma2(aa, kk2.x, s2[i][0]);
                s2[i][1] = fma2(aa, kk2.y, s2[i][1]);
            }
        }

        float tv[4][4];
#pragma unroll
        for (int i = 0; i < 4; i++) {
            float2 p0 = unpack2(s2[i][0]);
            float2 p1 = unpack2(s2[i][1]);
            tv[i][0] = p0.x; tv[i][1] = p0.y; tv[i][2] = p1.x; tv[i][3] = p1.y;
        }

        // Apply mask: t = s*m + (m-1)*10000
#pragma unroll
        for (int i = 0; i < 4; i++) {
            int qr = ty * 4 + i;
            float4 mv = *(const float4*)(Mg + (size_t)qr * S_LEN + kt * 64 + tx * 4);
            tv[i][0] = tv[i][0] * mv.x + (mv.x - 1.0f) * 10000.0f;
            tv[i][1] = tv[i][1] * mv.y + (mv.y - 1.0f) * 10000.0f;
            tv[i][2] = tv[i][2] * mv.z + (mv.z - 1.0f) * 10000.0f;
            tv[i][3] = tv[i][3] * mv.w + (mv.w - 1.0f) * 10000.0f;
        }

        // Online softmax update (row stats shared across the 16 tx lanes)
#pragma unroll
        for (int i = 0; i < 4; i++) {
            float rmax = fmaxf(fmaxf(tv[i][0], tv[i][1]), fmaxf(tv[i][2], tv[i][3]));
            rmax = fmaxf(rmax, __shfl_xor_sync(0xffffffffu, rmax, 8));
            rmax = fmaxf(rmax, __shfl_xor_sync(0xffffffffu, rmax, 4));
            rmax = fmaxf(rmax, __shfl_xor_sync(0xffffffffu, rmax, 2));
            rmax = fmaxf(rmax, __shfl_xor_sync(0xffffffffu, rmax, 1));
            float mnew = fmaxf(m_i[i], rmax);
            float alpha = __expf(m_i[i] - mnew);
            m_i[i] = mnew;
            float p0 = __expf(tv[i][0] - mnew);
            float p1 = __expf(tv[i][1] - mnew);
            float p2 = __expf(tv[i][2] - mnew);
            float p3 = __expf(tv[i][3] - mnew);
            float rsum = p0 + p1 + p2 + p3;
            rsum += __shfl_xor_sync(0xffffffffu, rsum, 8);
            rsum += __shfl_xor_sync(0xffffffffu, rsum, 4);
            rsum += __shfl_xor_sync(0xffffffffu, rsum, 2);
            rsum += __shfl_xor_sync(0xffffffffu, rsum, 1);
            l_i[i] = l_i[i] * alpha + rsum;
            unsigned long long av = pack2(alpha, alpha);
            acc[i][0] = mul2(acc[i][0], av);
            acc[i][1] = mul2(acc[i][1], av);
            float4 pv = {p0, p1, p2, p3};
            *(float4*)&Ps[(ty * 4 + i) * 68 + tx * 4] = pv;
        }
        __syncthreads();

        // O += P @ V (contraction over k)
#pragma unroll 16
        for (int kk = 0; kk < 64; kk++) {
            ulonglong2 vv2 = *(const ulonglong2*)&Vs[kk * 68 + tx * 4];
#pragma unroll
            for (int i = 0; i < 4; i++) {
                float pp = Ps[(ty * 4 + i) * 68 + kk];
                unsigned long long aa = pack2(pp, pp);
                acc[i][0] = fma2(aa, vv2.x, acc[i][0]);
                acc[i][1] = fma2(aa, vv2.y, acc[i][1]);
            }
        }
    }

    // Normalize and store to [B,S,D] scratch
#pragma unroll
    for (int i = 0; i < 4; i++) {
        float inv = 1.0f / l_i[i];
        float2 p0 = unpack2(acc[i][0]);
        float2 p1 = unpack2(acc[i][1]);
        float4 o = {p0.x * inv, p0.y * inv, p1.x * inv, p1.y * inv};
        int qr = q0 + ty * 4 + i;
        *(float4*)&g_attn[((size_t)b * S_LEN + qr) * DMODEL + h * DHEAD + tx * 4] = o;
    }
}

// ============================================================================
// Launch
// ============================================================================
extern "C" void kernel_launch(void* const* d_in, const int* in_sizes, int n_in,
                              void* d_out, int out_size)
{
    const float* src  = (const float*)d_in[0];
    const float* mask = (const float*)d_in[1];
    const float* Wqkv = (const float*)d_in[2];
    const float* bqkv = (const float*)d_in[3];
    const float* Wout = (const float*)d_in[4];
    const float* bout = (const float*)d_in[5];
    float* out = (float*)d_out;

    dim3 blk(256);

    // QKV projection, scattered into [B,H,S,dh] scratch
    sgemm_kernel<0><<<dim3(3072 / 128, 4096 / 128), blk>>>(
        src, Wqkv, bqkv, nullptr, BATCH * S_LEN, 3 * DMODEL, DMODEL);

    // Fused masked attention
    int smem = 4 * 64 * 68 * (int)sizeof(float);  // 69,632 B
    cudaFuncSetAttribute(flash_kernel, cudaFuncAttributeMaxDynamicSharedMemorySize, smem);
    flash_kernel<<<dim3(S_LEN / 64, NHEAD, BATCH), blk, smem>>>(mask);

    // Output projection
    sgemm_kernel<2><<<dim3(1024 / 128, 4096 / 128), blk>>>(
        nullptr, Wout, bout, out, BATCH * S_LEN, DMODEL, DMODEL);
}

// round 4
// speedup vs baseline: 1.5436x; 1.5436x over previous
#include <cuda_runtime.h>
#include <cstdint>

#define S_LEN  2048
#define DMODEL 1024
#define NHEAD  16
#define DHEAD  64
#define BATCH  2
#define MTOT   (BATCH * S_LEN)        // 4096

// Scratch (static device globals — no runtime allocation).
__device__ float g_q[BATCH * NHEAD * S_LEN * DHEAD];
__device__ float g_k[BATCH * NHEAD * S_LEN * DHEAD];
__device__ float g_v[BATCH * NHEAD * S_LEN * DHEAD];
__device__ float g_attn[BATCH * S_LEN * DMODEL];
__device__ float g_aperm[MTOT * DMODEL];          // A in fragment layout (16MB)
__device__ float g_bqkvP[DMODEL * 3 * DMODEL];    // W_qkv in B-frag layout
__device__ float g_boutP[DMODEL * DMODEL];        // W_out in B-frag layout

// ============================ helpers ============================
__device__ __forceinline__ uint32_t smem_u32(const void* p) {
    uint32_t a;
    asm("{ .reg .u64 t; cvta.to.shared.u64 t, %1; cvt.u32.u64 %0, t; }" : "=r"(a) : "l"(p));
    return a;
}
__device__ __forceinline__ uint32_t f2tf32(float f) {
    uint32_t r; asm("cvt.rna.tf32.f32 %0, %1;" : "=r"(r) : "f"(f)); return r;
}
__device__ __forceinline__ void lds128(uint32_t a, uint32_t& r0, uint32_t& r1,
                                       uint32_t& r2, uint32_t& r3) {
    asm volatile("ld.shared.v4.b32 {%0,%1,%2,%3}, [%4];"
                 : "=r"(r0), "=r"(r1), "=r"(r2), "=r"(r3) : "r"(a));
}
__device__ __forceinline__ void lds64(uint32_t a, uint32_t& r0, uint32_t& r1) {
    asm volatile("ld.shared.v2.b32 {%0,%1}, [%2];" : "=r"(r0), "=r"(r1) : "r"(a));
}
__device__ __forceinline__ void cp16(uint32_t saddr, const void* gaddr) {
    asm volatile("cp.async.cg.shared.global [%0], [%1], 16;" :: "r"(saddr), "l"(gaddr));
}
#define CP_COMMIT() asm volatile("cp.async.commit_group;" ::: "memory")
#define CP_WAIT1()  asm volatile("cp.async.wait_group 1;" ::: "memory")

__device__ __forceinline__ void mma_tf32(float c[4], uint32_t a0, uint32_t a1,
                                         uint32_t a2, uint32_t a3,
                                         uint32_t b0, uint32_t b1) {
    asm volatile(
        "mma.sync.aligned.m16n8k8.row.col.f32.tf32.tf32.f32 "
        "{%0,%1,%2,%3}, {%4,%5,%6,%7}, {%8,%9}, {%0,%1,%2,%3};"
        : "+f"(c[0]), "+f"(c[1]), "+f"(c[2]), "+f"(c[3])
        : "r"(a0), "r"(a1), "r"(a2), "r"(a3), "r"(b0), "r"(b1));
}

// ---- packed f32x2 helpers (flash kernel) ----
__device__ __forceinline__ unsigned long long pack2(float lo, float hi) {
    unsigned long long r; asm("mov.b64 %0, {%1, %2};" : "=l"(r) : "f"(lo), "f"(hi)); return r;
}
__device__ __forceinline__ float2 unpack2(unsigned long long v) {
    float2 f; asm("mov.b64 {%0, %1}, %2;" : "=f"(f.x), "=f"(f.y) : "l"(v)); return f;
}
__device__ __forceinline__ unsigned long long fma2(unsigned long long a, unsigned long long b,
                                                   unsigned long long c) {
    unsigned long long d; asm("fma.rn.f32x2 %0, %1, %2, %3;" : "=l"(d) : "l"(a), "l"(b), "l"(c)); return d;
}
__device__ __forceinline__ unsigned long long mul2(unsigned long long a, unsigned long long b) {
    unsigned long long d; asm("mul.rn.f32x2 %0, %1, %2;" : "=l"(d) : "l"(a), "l"(b)); return d;
}

// ============================================================================
// permA: A[M=4096][K=1024] row-major -> fragment-layout chunks (tf32-rounded).
// chunk c (16B): [mb(32)][kc(32)][k8(4)][wm(2)][mt(4)][lane(32)] ; lane=(g<<2)|t
//   f0=A[m][k] f1=A[m+8][k] f2=A[m][k+4] f3=A[m+8][k+4]
//   m = mb*128+wm*64+mt*16+g ; k = kc*32+k8*8+t
// ============================================================================
__global__ __launch_bounds__(256) void permA_kernel(
    const float* __restrict__ A, float* __restrict__ out)
{
    uint32_t c = blockIdx.x * 256 + threadIdx.x;
    uint32_t lane = c & 31, mt = (c >> 5) & 3, wm = (c >> 7) & 1;
    uint32_t k8 = (c >> 8) & 3, kc = (c >> 10) & 31, mb = c >> 15;
    uint32_t g = lane >> 2, t = lane & 3;
    uint32_t m = mb * 128 + wm * 64 + mt * 16 + g;
    uint32_t k = kc * 32 + k8 * 8 + t;
    const float* Ap = A + (size_t)m * DMODEL + k;
    uint4 o;
    o.x = f2tf32(Ap[0]);
    o.y = f2tf32(Ap[8 * DMODEL]);
    o.z = f2tf32(Ap[4]);
    o.w = f2tf32(Ap[8 * DMODEL + 4]);
    *(uint4*)(out + (size_t)c * 4) = o;
}

// ============================================================================
// permB: W[K=1024][N] row-major -> B-frag chunks (8B), tf32-rounded.
// chunk c: [nb][kc(32)][k8(4)][wn(4)][nt(4)][lane(32)]
//   f0=W[k][n] f1=W[k+4][n]; n = nb*128+wn*32+nt*8+g ; k = kc*32+k8*8+t
// ============================================================================
__global__ __launch_bounds__(256) void permB_kernel(
    const float* __restrict__ W, float* __restrict__ out, int N)
{
    uint32_t c = blockIdx.x * 256 + threadIdx.x;
    uint32_t lane = c & 31, nt = (c >> 5) & 3, wn = (c >> 7) & 3;
    uint32_t k8 = (c >> 9) & 3, kc = (c >> 11) & 31, nb = c >> 16;
    uint32_t g = lane >> 2, t = lane & 3;
    uint32_t n = nb * 128 + wn * 32 + nt * 8 + g;
    uint32_t k = kc * 32 + k8 * 8 + t;
    uint2 o;
    o.x = f2tf32(W[(size_t)k * N + n]);
    o.y = f2tf32(W[(size_t)(k + 4) * N + n]);
    *(uint2*)(out + (size_t)c * 2) = o;
}

// ============================================================================
// mma.sync tf32 GEMM. CTA 128x128, 8 warps (wm = wid&1 -> 64 rows,
// wn = wid>>1 -> 32 cols). K staged in chunks of 32 via cp.async, 2 stages.
// MODE 0: scatter +bias into g_q/g_k/g_v as [B,H,S,dh]
// MODE 2: plain row-major store +bias
// ============================================================================
#define STAGE_BYTES 32768   // 16KB A + 16KB B

template <int MODE>
__global__ __launch_bounds__(256, 2) void mma_gemm(
    const float* __restrict__ Aperm, const float* __restrict__ Bperm,
    const float* __restrict__ bias, float* __restrict__ C, int N)
{
    extern __shared__ char smem[];
    const uint32_t sbase = smem_u32(smem);

    int tid = threadIdx.x;
    int wid = tid >> 5, lane = tid & 31;
    int wm = wid & 1, wn = wid >> 1;
    int g = lane >> 2, t = lane & 3;
    int nb = blockIdx.x, mb = blockIdx.y;
    int nchunks = DMODEL / 32;   // 32

    const char* Ag = (const char*)(Aperm) + ((size_t)mb * nchunks) * 16384;
    const char* Bg = (const char*)(Bperm) + ((size_t)nb * nchunks) * 16384;

    float c[4][4][4];
#pragma unroll
    for (int i = 0; i < 4; i++)
#pragma unroll
        for (int j = 0; j < 4; j++)
#pragma unroll
            for (int q = 0; q < 4; q++) c[i][j][q] = 0.0f;

    // stage copy: thread copies 4x16B of A and 4x16B of B
    auto load_stage = [&](int kc, int buf) {
        uint32_t s = sbase + buf * STAGE_BYTES;
        const char* a = Ag + (size_t)kc * 16384;
        const char* b = Bg + (size_t)kc * 16384;
#pragma unroll
        for (int i = 0; i < 4; i++) {
            int off = (tid + i * 256) * 16;
            cp16(s + off, a + off);
            cp16(s + 16384 + off, b + off);
        }
    };

    load_stage(0, 0); CP_COMMIT();
    load_stage(1, 1); CP_COMMIT();

    for (int kc = 0; kc < nchunks; kc++) {
        CP_WAIT1();
        __syncthreads();
        int buf = kc & 1;
        uint32_t aS = sbase + buf * STAGE_BYTES;
        uint32_t bS = aS + 16384;
#pragma unroll
        for (int k8 = 0; k8 < 4; k8++) {
            uint32_t a0[4], a1[4], a2[4], a3[4], b0[4], b1[4];
#pragma unroll
            for (int mt = 0; mt < 4; mt++)
                lds128(aS + (((k8 * 2 + wm) * 4 + mt) * 32 + lane) * 16,
                       a0[mt], a1[mt], a2[mt], a3[mt]);
#pragma unroll
            for (int nt = 0; nt < 4; nt++)
                lds64(bS + (((k8 * 4 + wn) * 4 + nt) * 32 + lane) * 8,
                      b0[nt], b1[nt]);
#pragma unroll
            for (int mt = 0; mt < 4; mt++)
#pragma unroll
                for (int nt = 0; nt < 4; nt++)
                    mma_tf32(c[mt][nt], a0[mt], a1[mt], a2[mt], a3[mt],
                             b0[nt], b1[nt]);
        }
        __syncthreads();
        if (kc + 2 < nchunks) load_stage(kc + 2, buf);
        CP_COMMIT();
    }

    // Epilogue
    int bm = mb * 128, bn = nb * 128;
#pragma unroll
    for (int mt = 0; mt < 4; mt++) {
        int r0 = bm + wm * 64 + mt * 16 + g;
        int r1 = r0 + 8;
#pragma unroll
        for (int nt = 0; nt < 4; nt++) {
            int col = bn + wn * 32 + nt * 8 + 2 * t;
            float bx = bias[col], by = bias[col + 1];
            float2 lo = {c[mt][nt][0] + bx, c[mt][nt][1] + by};
            float2 hi = {c[mt][nt][2] + bx, c[mt][nt][3] + by};
            if (MODE == 2) {
                *(float2*)&C[(size_t)r0 * N + col] = lo;
                *(float2*)&C[(size_t)r1 * N + col] = hi;
            } else {
                float* dstb = (col < 1024) ? g_q : (col < 2048 ? g_k : g_v);
                int w = col & 1023;
                int h = w >> 6, d0 = w & 63;
                {
                    int b = r0 >> 11, s = r0 & 2047;
                    *(float2*)&dstb[(((size_t)b * NHEAD + h) * S_LEN + s) * DHEAD + d0] = lo;
                }
                {
                    int b = r1 >> 11, s = r1 & 2047;
                    *(float2*)&dstb[(((size_t)b * NHEAD + h) * S_LEN + s) * DHEAD + d0] = hi;
                }
            }
        }
    }
}

// ============================================================================
// Flash attention (unchanged, known-good): block per (64-q tile, head, batch).
// ============================================================================
__global__ __launch_bounds__(256) void flash_kernel(const float* __restrict__ mask)
{
    extern __shared__ float sm[];
    float* Qs = sm;
    float* Ks = sm + 64 * 68;
    float* Vs = sm + 2 * 64 * 68;
    float* Ps = sm + 3 * 64 * 68;

    int tid = threadIdx.x;
    int tx = tid & 15, ty = tid >> 4;
    int q0 = blockIdx.x * 64;
    int h = blockIdx.y, b = blockIdx.z;

    const float* Qg = g_q + (((size_t)b * NHEAD + h) * S_LEN + q0) * DHEAD;
    const float* Kg = g_k + ((size_t)b * NHEAD + h) * S_LEN * DHEAD;
    const float* Vg = g_v + ((size_t)b * NHEAD + h) * S_LEN * DHEAD;
    const float* Mg = mask + (size_t)b * S_LEN * S_LEN + (size_t)q0 * S_LEN;

#pragma unroll
    for (int t = 0; t < 4; t++) {
        int fidx = tid + t * 256;
        int row = fidx >> 4, c4 = (fidx & 15) * 4;
        float4 v = *(const float4*)(Qg + row * 64 + c4);
        v.x *= 0.125f; v.y *= 0.125f; v.z *= 0.125f; v.w *= 0.125f;
        *(float4*)&Qs[row * 68 + c4] = v;
    }

    unsigned long long acc[4][2];
    float m_i[4], l_i[4];
#pragma unroll
    for (int i = 0; i < 4; i++) {
        acc[i][0] = 0ULL; acc[i][1] = 0ULL;
        m_i[i] = -1e30f; l_i[i] = 0.0f;
    }

    for (int kt = 0; kt < S_LEN / 64; kt++) {
        __syncthreads();
#pragma unroll
        for (int t = 0; t < 4; t++) {
            int fidx = tid + t * 256;
            int row = fidx >> 4, c4 = (fidx & 15) * 4;
            float4 kv = *(const float4*)(Kg + (size_t)(kt * 64 + row) * 64 + c4);
            Ks[(c4 + 0) * 68 + row] = kv.x;
            Ks[(c4 + 1) * 68 + row] = kv.y;
            Ks[(c4 + 2) * 68 + row] = kv.z;
            Ks[(c4 + 3) * 68 + row] = kv.w;
            float4 vv = *(const float4*)(Vg + (size_t)(kt * 64 + row) * 64 + c4);
            *(float4*)&Vs[row * 68 + c4] = vv;
        }
        __syncthreads();

        unsigned long long s2[4][2];
#pragma unroll
        for (int i = 0; i < 4; i++) { s2[i][0] = 0ULL; s2[i][1] = 0ULL; }
#pragma unroll 16
        for (int d = 0; d < 64; d++) {
            ulonglong2 kk2 = *(const ulonglong2*)&Ks[d * 68 + tx * 4];
#pragma unroll
            for (int i = 0; i < 4; i++) {
                float qv = Qs[(ty * 4 + i) * 68 + d];
                unsigned long long aa = pack2(qv, qv);
                s2[i][0] = fma2(aa, kk2.x, s2[i][0]);
                s2[i][1] = fma2(aa, kk2.y, s2[i][1]);
            }
        }

        float tv[4][4];
#pragma unroll
        for (int i = 0; i < 4; i++) {
            float2 p0 = unpack2(s2[i][0]);
            float2 p1 = unpack2(s2[i][1]);
            tv[i][0] = p0.x; tv[i][1] = p0.y; tv[i][2] = p1.x; tv[i][3] = p1.y;
        }

#pragma unroll
        for (int i = 0; i < 4; i++) {
            int qr = ty * 4 + i;
            float4 mv = *(const float4*)(Mg + (size_t)qr * S_LEN + kt * 64 + tx * 4);
            tv[i][0] = tv[i][0] * mv.x + (mv.x - 1.0f) * 10000.0f;
            tv[i][1] = tv[i][1] * mv.y + (mv.y - 1.0f) * 10000.0f;
            tv[i][2] = tv[i][2] * mv.z + (mv.z - 1.0f) * 10000.0f;
            tv[i][3] = tv[i][3] * mv.w + (mv.w - 1.0f) * 10000.0f;
        }

#pragma unroll
        for (int i = 0; i < 4; i++) {
            float rmax = fmaxf(fmaxf(tv[i][0], tv[i][1]), fmaxf(tv[i][2], tv[i][3]));
            rmax = fmaxf(rmax, __shfl_xor_sync(0xffffffffu, rmax, 8));
            rmax = fmaxf(rmax, __shfl_xor_sync(0xffffffffu, rmax, 4));
            rmax = fmaxf(rmax, __shfl_xor_sync(0xffffffffu, rmax, 2));
            rmax = fmaxf(rmax, __shfl_xor_sync(0xffffffffu, rmax, 1));
            float mnew = fmaxf(m_i[i], rmax);
            float alpha = __expf(m_i[i] - mnew);
            m_i[i] = mnew;
            float p0 = __expf(tv[i][0] - mnew);
            float p1 = __expf(tv[i][1] - mnew);
            float p2 = __expf(tv[i][2] - mnew);
            float p3 = __expf(tv[i][3] - mnew);
            float rsum = p0 + p1 + p2 + p3;
            rsum += __shfl_xor_sync(0xffffffffu, rsum, 8);
            rsum += __shfl_xor_sync(0xffffffffu, rsum, 4);
            rsum += __shfl_xor_sync(0xffffffffu, rsum, 2);
            rsum += __shfl_xor_sync(0xffffffffu, rsum, 1);
            l_i[i] = l_i[i] * alpha + rsum;
            unsigned long long av = pack2(alpha, alpha);
            acc[i][0] = mul2(acc[i][0], av);
            acc[i][1] = mul2(acc[i][1], av);
            float4 pv = {p0, p1, p2, p3};
            *(float4*)&Ps[(ty * 4 + i) * 68 + tx * 4] = pv;
        }
        __syncthreads();

#pragma unroll 16
        for (int kk = 0; kk < 64; kk++) {
            ulonglong2 vv2 = *(const ulonglong2*)&Vs[kk * 68 + tx * 4];
#pragma unroll
            for (int i = 0; i < 4; i++) {
                float pp = Ps[(ty * 4 + i) * 68 + kk];
                unsigned long long aa = pack2(pp, pp);
                acc[i][0] = fma2(aa, vv2.x, acc[i][0]);
                acc[i][1] = fma2(aa, vv2.y, acc[i][1]);
            }
        }
    }

#pragma unroll
    for (int i = 0; i < 4; i++) {
        float inv = 1.0f / l_i[i];
        float2 p0 = unpack2(acc[i][0]);
        float2 p1 = unpack2(acc[i][1]);
        float4 o = {p0.x * inv, p0.y * inv, p1.x * inv, p1.y * inv};
        int qr = q0 + ty * 4 + i;
        *(float4*)&g_attn[((size_t)b * S_LEN + qr) * DMODEL + h * DHEAD + tx * 4] = o;
    }
}

// ============================================================================
// Launch
// ============================================================================
extern "C" void kernel_launch(void* const* d_in, const int* in_sizes, int n_in,
                              void* d_out, int out_size)
{
    const float* src  = (const float*)d_in[0];
    const float* mask = (const float*)d_in[1];
    const float* Wqkv = (const float*)d_in[2];
    const float* bqkv = (const float*)d_in[3];
    const float* Wout = (const float*)d_in[4];
    const float* bout = (const float*)d_in[5];
    float* out = (float*)d_out;

    float* aperm; cudaGetSymbolAddress((void**)&aperm, g_aperm);
    float* bqkvP; cudaGetSymbolAddress((void**)&bqkvP, g_bqkvP);
    float* boutP; cudaGetSymbolAddress((void**)&boutP, g_boutP);
    float* attnL; cudaGetSymbolAddress((void**)&attnL, g_attn);

    cudaFuncSetAttribute(mma_gemm<0>, cudaFuncAttributeMaxDynamicSharedMemorySize, 2 * STAGE_BYTES);
    cudaFuncSetAttribute(mma_gemm<2>, cudaFuncAttributeMaxDynamicSharedMemorySize, 2 * STAGE_BYTES);

    // Weight + activation permutes (tf32-rounded, fragment layout)
    permB_kernel<<<DMODEL * 3 * DMODEL / 2 / 256, 256>>>(Wqkv, bqkvP, 3 * DMODEL);
    permB_kernel<<<DMODEL * DMODEL / 2 / 256, 256>>>(Wout, boutP, DMODEL);
    permA_kernel<<<MTOT * DMODEL / 4 / 256, 256>>>(src, aperm);

    // QKV projection -> scattered [B,H,S,dh]
    mma_gemm<0><<<dim3(3 * DMODEL / 128, MTOT / 128), 256, 2 * STAGE_BYTES>>>(
        aperm, bqkvP, bqkv, nullptr, 3 * DMODEL);

    // Fused masked attention
    int smem = 4 * 64 * 68 * (int)sizeof(float);
    cudaFuncSetAttribute(flash_kernel, cudaFuncAttributeMaxDynamicSharedMemorySize, smem);
    flash_kernel<<<dim3(S_LEN / 64, NHEAD, BATCH), 256, smem>>>(mask);

    // Output projection
    permA_kernel<<<MTOT * DMODEL / 4 / 256, 256>>>(attnL, aperm);
    mma_gemm<2><<<dim3(DMODEL / 128, MTOT / 128), 256, 2 * STAGE_BYTES>>>(
        aperm, boutP, bout, out, DMODEL);
}

// round 9
// speedup vs baseline: 3.2720x; 2.1197x over previous
#include <cuda_runtime.h>
#include <cstdint>

#define S_LEN  2048
#define DMODEL 1024
#define NHEAD  16
#define DHEAD  64
#define BATCH  2
#define MTOT   (BATCH * S_LEN)        // 4096

// Scratch (static device globals — no runtime allocation).
__device__ float g_q[BATCH * NHEAD * S_LEN * DHEAD];
__device__ float g_k[BATCH * NHEAD * S_LEN * DHEAD];
__device__ float g_v[BATCH * NHEAD * S_LEN * DHEAD];
__device__ float g_attn[BATCH * S_LEN * DMODEL];
__device__ float g_aperm[MTOT * DMODEL];          // GEMM A in fragment layout
__device__ float g_bqkvP[DMODEL * 3 * DMODEL];    // W_qkv in B-frag layout
__device__ float g_boutP[DMODEL * DMODEL];        // W_out in B-frag layout
__device__ float g_qf[BATCH * NHEAD * S_LEN * DHEAD];   // Q in A-frag layout
__device__ float g_kf[BATCH * NHEAD * S_LEN * DHEAD];   // K in B-frag layout
__device__ float g_vf[BATCH * NHEAD * S_LEN * DHEAD];   // V in B-frag layout

// ============================ helpers ============================
__device__ __forceinline__ uint32_t smem_u32(const void* p) {
    uint32_t a;
    asm("{ .reg .u64 t; cvta.to.shared.u64 t, %1; cvt.u32.u64 %0, t; }" : "=r"(a) : "l"(p));
    return a;
}
__device__ __forceinline__ uint32_t f2tf32(float f) {
    uint32_t r; asm("cvt.rna.tf32.f32 %0, %1;" : "=r"(r) : "f"(f)); return r;
}
__device__ __forceinline__ void lds128(uint32_t a, uint32_t& r0, uint32_t& r1,
                                       uint32_t& r2, uint32_t& r3) {
    asm volatile("ld.shared.v4.b32 {%0,%1,%2,%3}, [%4];"
                 : "=r"(r0), "=r"(r1), "=r"(r2), "=r"(r3) : "r"(a));
}
__device__ __forceinline__ void lds64(uint32_t a, uint32_t& r0, uint32_t& r1) {
    asm volatile("ld.shared.v2.b32 {%0,%1}, [%2];" : "=r"(r0), "=r"(r1) : "r"(a));
}
__device__ __forceinline__ float lds32f(uint32_t a) {
    float f; asm volatile("ld.shared.f32 %0, [%1];" : "=f"(f) : "r"(a)); return f;
}
__device__ __forceinline__ void sts64(uint32_t a, float f0, float f1) {
    asm volatile("st.shared.v2.f32 [%0], {%1,%2};" :: "r"(a), "f"(f0), "f"(f1) : "memory");
}
__device__ __forceinline__ void cp16(uint32_t saddr, const void* gaddr) {
    asm volatile("cp.async.cg.shared.global [%0], [%1], 16;" :: "r"(saddr), "l"(gaddr));
}
#define CP_COMMIT() asm volatile("cp.async.commit_group;" ::: "memory")
#define CP_WAIT1()  asm volatile("cp.async.wait_group 1;" ::: "memory")

__device__ __forceinline__ void mma_tf32(float c[4], uint32_t a0, uint32_t a1,
                                         uint32_t a2, uint32_t a3,
                                         uint32_t b0, uint32_t b1) {
    asm volatile(
        "mma.sync.aligned.m16n8k8.row.col.f32.tf32.tf32.f32 "
        "{%0,%1,%2,%3}, {%4,%5,%6,%7}, {%8,%9}, {%0,%1,%2,%3};"
        : "+f"(c[0]), "+f"(c[1]), "+f"(c[2]), "+f"(c[3])
        : "r"(a0), "r"(a1), "r"(a2), "r"(a3), "r"(b0), "r"(b1));
}

// ============================================================================
// permA: A[M=4096][K=1024] row-major -> A-frag chunks (tf32-rounded).
// ============================================================================
__global__ __launch_bounds__(256) void permA_kernel(
    const float* __restrict__ A, float* __restrict__ out)
{
    uint32_t c = blockIdx.x * 256 + threadIdx.x;
    uint32_t lane = c & 31, mt = (c >> 5) & 3, wm = (c >> 7) & 1;
    uint32_t k8 = (c >> 8) & 3, kc = (c >> 10) & 31, mb = c >> 15;
    uint32_t g = lane >> 2, t = lane & 3;
    uint32_t m = mb * 128 + wm * 64 + mt * 16 + g;
    uint32_t k = kc * 32 + k8 * 8 + t;
    const float* Ap = A + (size_t)m * DMODEL + k;
    uint4 o;
    o.x = f2tf32(Ap[0]);
    o.y = f2tf32(Ap[8 * DMODEL]);
    o.z = f2tf32(Ap[4]);
    o.w = f2tf32(Ap[8 * DMODEL + 4]);
    *(uint4*)(out + (size_t)c * 4) = o;
}

// ============================================================================
// permB: W[K=1024][N] row-major -> B-frag chunks (8B), tf32-rounded.
// ============================================================================
__global__ __launch_bounds__(256) void permB_kernel(
    const float* __restrict__ W, float* __restrict__ out, int N)
{
    uint32_t c = blockIdx.x * 256 + threadIdx.x;
    uint32_t lane = c & 31, nt = (c >> 5) & 3, wn = (c >> 7) & 3;
    uint32_t k8 = (c >> 9) & 3, kc = (c >> 11) & 31, nb = c >> 16;
    uint32_t g = lane >> 2, t = lane & 3;
    uint32_t n = nb * 128 + wn * 32 + nt * 8 + g;
    uint32_t k = kc * 32 + k8 * 8 + t;
    uint2 o;
    o.x = f2tf32(W[(size_t)k * N + n]);
    o.y = f2tf32(W[(size_t)(k + 4) * N + n]);
    *(uint2*)(out + (size_t)c * 2) = o;
}

// ============================================================================
// permQ: g_q [B,H,S,64] -> Q A-frag layout, scaled by 0.125, tf32.
// (smem pad = 68 floats: multiple of 4 keeps float4 accesses 16B-aligned.)
// ============================================================================
__global__ __launch_bounds__(256) void permQ_kernel()
{
    __shared__ float smt[64][68];
    int sub = blockIdx.x;        // 0..3  (64-row subtile of the 256-row block)
    int qb = blockIdx.y;         // 0..7
    int bh = blockIdx.z;         // 0..31
    int tid = threadIdx.x;
    size_t R0 = (size_t)bh * S_LEN + qb * 256 + sub * 64;
#pragma unroll
    for (int i = 0; i < 4; i++) {
        int idx = tid + i * 256;
        int r = idx >> 4, d4 = (idx & 15) * 4;
        *(float4*)&smt[r][d4] = *(const float4*)(g_q + (R0 + r) * 64 + d4);
    }
    __syncthreads();
#pragma unroll
    for (int i = 0; i < 4; i++) {
        uint32_t cl = tid + i * 256;            // 0..1023
        uint32_t lane = cl & 31, mt = (cl >> 5) & 1, k8 = (cl >> 6) & 7, wl = (cl >> 9) & 1;
        uint32_t g = lane >> 2, t = lane & 3;
        uint32_t rl = wl * 32 + mt * 16 + g;
        uint32_t k = k8 * 8 + t;
        uint4 o;
        o.x = f2tf32(smt[rl][k] * 0.125f);
        o.y = f2tf32(smt[rl + 8][k] * 0.125f);
        o.z = f2tf32(smt[rl][k + 4] * 0.125f);
        o.w = f2tf32(smt[rl + 8][k + 4] * 0.125f);
        uint32_t w = sub * 2 + wl;
        size_t C = (((((size_t)bh * 8 + qb) * 8 + w) * 8 + k8) * 2 + mt) * 32 + lane;
        *(uint4*)(g_qf + C * 4) = o;
    }
}

// ============================================================================
// permKV: per (kt, bh) tile of 64 keys. (pad 68, see permQ)
//   K frag: f0=K[key=nt*8+g][dim=k8*8+t], f1=dim+4   (B-frag, k=dim,n=key)
//   V frag: f0=V[key=k8*8+t][dim=nt*8+g], f1=key+4   (B-frag, k=key,n=dim)
// base is a CHUNK index (2 floats/chunk): tile stride = 2048 chunks = 4096 floats.
// ============================================================================
__global__ __launch_bounds__(256) void permKV_kernel()
{
    __shared__ float sk[64][68];
    __shared__ float sv[64][68];
    int kt = blockIdx.x;         // 0..31
    int bh = blockIdx.y;         // 0..31
    int tid = threadIdx.x;
    size_t R0 = (size_t)bh * S_LEN + kt * 64;
#pragma unroll
    for (int i = 0; i < 4; i++) {
        int idx = tid + i * 256;
        int r = idx >> 4, d4 = (idx & 15) * 4;
        *(float4*)&sk[r][d4] = *(const float4*)(g_k + (R0 + r) * 64 + d4);
        *(float4*)&sv[r][d4] = *(const float4*)(g_v + (R0 + r) * 64 + d4);
    }
    __syncthreads();
    size_t base = ((size_t)bh * 32 + kt) * 2048;   // chunk index (FIX: was *4096)
#pragma unroll
    for (int i = 0; i < 8; i++) {
        uint32_t cl = tid + i * 256;            // 0..2047
        uint32_t lane = cl & 31, nt = (cl >> 5) & 7, k8 = (cl >> 8) & 7;
        uint32_t g = lane >> 2, t = lane & 3;
        uint2 ok, ov;
        ok.x = f2tf32(sk[nt * 8 + g][k8 * 8 + t]);
        ok.y = f2tf32(sk[nt * 8 + g][k8 * 8 + t + 4]);
        ov.x = f2tf32(sv[k8 * 8 + t][nt * 8 + g]);
        ov.y = f2tf32(sv[k8 * 8 + t + 4][nt * 8 + g]);
        *(uint2*)(g_kf + (base + cl) * 2) = ok;
        *(uint2*)(g_vf + (base + cl) * 2) = ov;
    }
}

// ============================================================================
// mma.sync tf32 GEMM (unchanged, validated in R4).
// ============================================================================
#define STAGE_BYTES 32768

template <int MODE>
__global__ __launch_bounds__(256, 2) void mma_gemm(
    const float* __restrict__ Aperm, const float* __restrict__ Bperm,
    const float* __restrict__ bias, float* __restrict__ C, int N)
{
    extern __shared__ char smem[];
    const uint32_t sbase = smem_u32(smem);

    int tid = threadIdx.x;
    int wid = tid >> 5, lane = tid & 31;
    int wm = wid & 1, wn = wid >> 1;
    int g = lane >> 2, t = lane & 3;
    int nb = blockIdx.x, mb = blockIdx.y;
    int nchunks = DMODEL / 32;

    const char* Ag = (const char*)(Aperm) + ((size_t)mb * nchunks) * 16384;
    const char* Bg = (const char*)(Bperm) + ((size_t)nb * nchunks) * 16384;

    float c[4][4][4];
#pragma unroll
    for (int i = 0; i < 4; i++)
#pragma unroll
        for (int j = 0; j < 4; j++)
#pragma unroll
            for (int q = 0; q < 4; q++) c[i][j][q] = 0.0f;

    auto load_stage = [&](int kc, int buf) {
        uint32_t s = sbase + buf * STAGE_BYTES;
        const char* a = Ag + (size_t)kc * 16384;
        const char* b = Bg + (size_t)kc * 16384;
#pragma unroll
        for (int i = 0; i < 4; i++) {
            int off = (tid + i * 256) * 16;
            cp16(s + off, a + off);
            cp16(s + 16384 + off, b + off);
        }
    };

    load_stage(0, 0); CP_COMMIT();
    load_stage(1, 1); CP_COMMIT();

    for (int kc = 0; kc < nchunks; kc++) {
        CP_WAIT1();
        __syncthreads();
        int buf = kc & 1;
        uint32_t aS = sbase + buf * STAGE_BYTES;
        uint32_t bS = aS + 16384;
#pragma unroll
        for (int k8 = 0; k8 < 4; k8++) {
            uint32_t a0[4], a1[4], a2[4], a3[4], b0[4], b1[4];
#pragma unroll
            for (int mt = 0; mt < 4; mt++)
                lds128(aS + (((k8 * 2 + wm) * 4 + mt) * 32 + lane) * 16,
                       a0[mt], a1[mt], a2[mt], a3[mt]);
#pragma unroll
            for (int nt = 0; nt < 4; nt++)
                lds64(bS + (((k8 * 4 + wn) * 4 + nt) * 32 + lane) * 8,
                      b0[nt], b1[nt]);
#pragma unroll
            for (int mt = 0; mt < 4; mt++)
#pragma unroll
                for (int nt = 0; nt < 4; nt++)
                    mma_tf32(c[mt][nt], a0[mt], a1[mt], a2[mt], a3[mt],
                             b0[nt], b1[nt]);
        }
        __syncthreads();
        if (kc + 2 < nchunks) load_stage(kc + 2, buf);
        CP_COMMIT();
    }

    int bm = mb * 128, bn = nb * 128;
#pragma unroll
    for (int mt = 0; mt < 4; mt++) {
        int r0 = bm + wm * 64 + mt * 16 + g;
        int r1 = r0 + 8;
#pragma unroll
        for (int nt = 0; nt < 4; nt++) {
            int col = bn + wn * 32 + nt * 8 + 2 * t;
            float bx = bias[col], by = bias[col + 1];
            float2 lo = {c[mt][nt][0] + bx, c[mt][nt][1] + by};
            float2 hi = {c[mt][nt][2] + bx, c[mt][nt][3] + by};
            if (MODE == 2) {
                *(float2*)&C[(size_t)r0 * N + col] = lo;
                *(float2*)&C[(size_t)r1 * N + col] = hi;
            } else {
                float* dstb = (col < 1024) ? g_q : (col < 2048 ? g_k : g_v);
                int w = col & 1023;
                int h = w >> 6, d0 = w & 63;
                {
                    int b = r0 >> 11, s = r0 & 2047;
                    *(float2*)&dstb[(((size_t)b * NHEAD + h) * S_LEN + s) * DHEAD + d0] = lo;
                }
                {
                    int b = r1 >> 11, s = r1 & 2047;
                    *(float2*)&dstb[(((size_t)b * NHEAD + h) * S_LEN + s) * DHEAD + d0] = hi;
                }
            }
        }
    }
}

// ============================================================================
// Flash attention with mma.sync tf32.
// Block: 256 q rows × one (b,h). 8 warps × 32 rows (mt=2). 64-key tiles,
// cp.async double-buffered K/V frags. P staged via per-warp smem (pad 68).
// smem: Q frags 64KB | KV 2×32KB | P 8×8704B  = 200704 B.
// ============================================================================
#define FLASH_SMEM 200704

__global__ __launch_bounds__(256) void flash_mma(const float* __restrict__ mask)
{
    extern __shared__ char smem[];
    const uint32_t uQ  = smem_u32(smem);
    const uint32_t uKV = uQ + 65536;
    const uint32_t uPb = uQ + 131072;

    int tid = threadIdx.x, wid = tid >> 5, lane = tid & 31;
    int g = lane >> 2, t = lane & 3;
    int qb = blockIdx.x, h = blockIdx.y, b = blockIdx.z;
    int bh = b * NHEAD + h;

    const float* qf = g_qf + ((size_t)bh * 8 + qb) * 16384;
    const float* kf = g_kf + (size_t)bh * (32 * 4096);
    const float* vf = g_vf + (size_t)bh * (32 * 4096);

    // Q frags -> smem (64KB)
#pragma unroll
    for (int i = 0; i < 16; i++) {
        int c = tid + i * 256;
        cp16(uQ + c * 16, qf + (size_t)c * 4);
    }
    auto stage_load = [&](int kt, int s) {
        uint32_t d = uKV + s * 32768;
        const float* kp = kf + (size_t)kt * 4096;
        const float* vp = vf + (size_t)kt * 4096;
#pragma unroll
        for (int i = 0; i < 4; i++) {
            int c = tid + i * 256;
            cp16(d + c * 16, kp + (size_t)c * 4);
            cp16(d + 16384 + c * 16, vp + (size_t)c * 4);
        }
    };
    stage_load(0, 0); CP_COMMIT();
    stage_load(1, 1); CP_COMMIT();

    float o[2][8][4];
    float m_i[2][2], l_i[2][2];
#pragma unroll
    for (int mt = 0; mt < 2; mt++) {
        m_i[mt][0] = -1e30f; m_i[mt][1] = -1e30f;
        l_i[mt][0] = 0.0f;   l_i[mt][1] = 0.0f;
#pragma unroll
        for (int nt = 0; nt < 8; nt++)
#pragma unroll
            for (int q = 0; q < 4; q++) o[mt][nt][q] = 0.0f;
    }

    const uint32_t uP = uPb + wid * 8704;
    const float* Mbase = mask + (size_t)b * S_LEN * S_LEN;
    int qr_base = qb * 256 + wid * 32;

    for (int kt = 0; kt < 32; kt++) {
        CP_WAIT1();
        __syncthreads();
        int buf = kt & 1;
        uint32_t uK = uKV + buf * 32768;
        uint32_t uV = uK + 16384;

        // ---- S = Q @ K^T ----
        float c[2][8][4];
#pragma unroll
        for (int mt = 0; mt < 2; mt++)
#pragma unroll
            for (int nt = 0; nt < 8; nt++)
#pragma unroll
                for (int q = 0; q < 4; q++) c[mt][nt][q] = 0.0f;
#pragma unroll
        for (int k8 = 0; k8 < 8; k8++) {
            uint32_t a[2][4];
#pragma unroll
            for (int mt = 0; mt < 2; mt++)
                lds128(uQ + (((wid * 16 + k8 * 2 + mt) * 32) + lane) * 16,
                       a[mt][0], a[mt][1], a[mt][2], a[mt][3]);
#pragma unroll
            for (int nt = 0; nt < 8; nt++) {
                uint32_t b0, b1;
                lds64(uK + ((k8 * 8 + nt) * 32 + lane) * 8, b0, b1);
                mma_tf32(c[0][nt], a[0][0], a[0][1], a[0][2], a[0][3], b0, b1);
                mma_tf32(c[1][nt], a[1][0], a[1][1], a[1][2], a[1][3], b0, b1);
            }
        }

        // ---- mask + online softmax + P store ----
#pragma unroll
        for (int mt = 0; mt < 2; mt++) {
            int qr = qr_base + mt * 16 + g;
            const float* M0 = Mbase + (size_t)qr * S_LEN + kt * 64 + 2 * t;
            const float* M1 = M0 + 8 * S_LEN;
            float mx0 = -1e30f, mx1 = -1e30f;
#pragma unroll
            for (int nt = 0; nt < 8; nt++) {
                float2 mv0 = *(const float2*)(M0 + nt * 8);
                float2 mv1 = *(const float2*)(M1 + nt * 8);
                c[mt][nt][0] = c[mt][nt][0] * mv0.x + (mv0.x - 1.0f) * 10000.0f;
                c[mt][nt][1] = c[mt][nt][1] * mv0.y + (mv0.y - 1.0f) * 10000.0f;
                c[mt][nt][2] = c[mt][nt][2] * mv1.x + (mv1.x - 1.0f) * 10000.0f;
                c[mt][nt][3] = c[mt][nt][3] * mv1.y + (mv1.y - 1.0f) * 10000.0f;
                mx0 = fmaxf(mx0, fmaxf(c[mt][nt][0], c[mt][nt][1]));
                mx1 = fmaxf(mx1, fmaxf(c[mt][nt][2], c[mt][nt][3]));
            }
            mx0 = fmaxf(mx0, __shfl_xor_sync(0xffffffffu, mx0, 1));
            mx0 = fmaxf(mx0, __shfl_xor_sync(0xffffffffu, mx0, 2));
            mx1 = fmaxf(mx1, __shfl_xor_sync(0xffffffffu, mx1, 1));
            mx1 = fmaxf(mx1, __shfl_xor_sync(0xffffffffu, mx1, 2));
            float mn0 = fmaxf(m_i[mt][0], mx0);
            float mn1 = fmaxf(m_i[mt][1], mx1);
            float al0 = __expf(m_i[mt][0] - mn0);
            float al1 = __expf(m_i[mt][1] - mn1);
            m_i[mt][0] = mn0; m_i[mt][1] = mn1;
            float s0 = 0.0f, s1 = 0.0f;
#pragma unroll
            for (int nt = 0; nt < 8; nt++) {
                float p0 = __expf(c[mt][nt][0] - mn0);
                float p1 = __expf(c[mt][nt][1] - mn0);
                float p2 = __expf(c[mt][nt][2] - mn1);
                float p3 = __expf(c[mt][nt][3] - mn1);
                s0 += p0 + p1; s1 += p2 + p3;
                sts64(uP + ((mt * 16 + g) * 68 + nt * 8 + 2 * t) * 4, p0, p1);
                sts64(uP + ((mt * 16 + g + 8) * 68 + nt * 8 + 2 * t) * 4, p2, p3);
            }
            s0 += __shfl_xor_sync(0xffffffffu, s0, 1);
            s0 += __shfl_xor_sync(0xffffffffu, s0, 2);
            s1 += __shfl_xor_sync(0xffffffffu, s1, 1);
            s1 += __shfl_xor_sync(0xffffffffu, s1, 2);
            l_i[mt][0] = l_i[mt][0] * al0 + s0;
            l_i[mt][1] = l_i[mt][1] * al1 + s1;
#pragma unroll
            for (int nt = 0; nt < 8; nt++) {
                o[mt][nt][0] *= al0; o[mt][nt][1] *= al0;
                o[mt][nt][2] *= al1; o[mt][nt][3] *= al1;
            }
        }
        __syncwarp();

        // ---- O += P @ V ----
#pragma unroll
        for (int k8 = 0; k8 < 8; k8++) {
            uint32_t a[2][4];
#pragma unroll
            for (int mt = 0; mt < 2; mt++) {
                a[mt][0] = __float_as_uint(lds32f(uP + ((mt * 16 + g) * 68 + k8 * 8 + t) * 4));
                a[mt][1] = __float_as_uint(lds32f(uP + ((mt * 16 + g + 8) * 68 + k8 * 8 + t) * 4));
                a[mt][2] = __float_as_uint(lds32f(uP + ((mt * 16 + g) * 68 + k8 * 8 + t + 4) * 4));
                a[mt][3] = __float_as_uint(lds32f(uP + ((mt * 16 + g + 8) * 68 + k8 * 8 + t + 4) * 4));
            }
#pragma unroll
            for (int nt = 0; nt < 8; nt++) {
                uint32_t b0, b1;
                lds64(uV + ((k8 * 8 + nt) * 32 + lane) * 8, b0, b1);
                mma_tf32(o[0][nt], a[0][0], a[0][1], a[0][2], a[0][3], b0, b1);
                mma_tf32(o[1][nt], a[1][0], a[1][1], a[1][2], a[1][3], b0, b1);
            }
        }
        __syncwarp();

        __syncthreads();
        if (kt + 2 < 32) stage_load(kt + 2, buf);
        CP_COMMIT();
    }

    // ---- normalize + store ----
#pragma unroll
    for (int mt = 0; mt < 2; mt++) {
        float inv0 = 1.0f / l_i[mt][0];
        float inv1 = 1.0f / l_i[mt][1];
        int qg0 = qr_base + mt * 16 + g;
        int qg1 = qg0 + 8;
#pragma unroll
        for (int nt = 0; nt < 8; nt++) {
            int col = h * 64 + nt * 8 + 2 * t;
            float2 lo = {o[mt][nt][0] * inv0, o[mt][nt][1] * inv0};
            float2 hi = {o[mt][nt][2] * inv1, o[mt][nt][3] * inv1};
            *(float2*)&g_attn[((size_t)b * S_LEN + qg0) * DMODEL + col] = lo;
            *(float2*)&g_attn[((size_t)b * S_LEN + qg1) * DMODEL + col] = hi;
        }
    }
}

// ============================================================================
// Launch
// ============================================================================
extern "C" void kernel_launch(void* const* d_in, const int* in_sizes, int n_in,
                              void* d_out, int out_size)
{
    const float* src  = (const float*)d_in[0];
    const float* mask = (const float*)d_in[1];
    const float* Wqkv = (const float*)d_in[2];
    const float* bqkv = (const float*)d_in[3];
    const float* Wout = (const float*)d_in[4];
    const float* bout = (const float*)d_in[5];
    float* out = (float*)d_out;

    float* aperm; cudaGetSymbolAddress((void**)&aperm, g_aperm);
    float* bqkvP; cudaGetSymbolAddress((void**)&bqkvP, g_bqkvP);
    float* boutP; cudaGetSymbolAddress((void**)&boutP, g_boutP);
    float* attnL; cudaGetSymbolAddress((void**)&attnL, g_attn);

    cudaFuncSetAttribute(mma_gemm<0>, cudaFuncAttributeMaxDynamicSharedMemorySize, 2 * STAGE_BYTES);
    cudaFuncSetAttribute(mma_gemm<2>, cudaFuncAttributeMaxDynamicSharedMemorySize, 2 * STAGE_BYTES);
    cudaFuncSetAttribute(flash_mma, cudaFuncAttributeMaxDynamicSharedMemorySize, FLASH_SMEM);

    // Weight + activation permutes
    permB_kernel<<<DMODEL * 3 * DMODEL / 2 / 256, 256>>>(Wqkv, bqkvP, 3 * DMODEL);
    permB_kernel<<<DMODEL * DMODEL / 2 / 256, 256>>>(Wout, boutP, DMODEL);
    permA_kernel<<<MTOT * DMODEL / 4 / 256, 256>>>(src, aperm);

    // QKV projection -> scattered [B,H,S,dh]
    mma_gemm<0><<<dim3(3 * DMODEL / 128, MTOT / 128), 256, 2 * STAGE_BYTES>>>(
        aperm, bqkvP, bqkv, nullptr, 3 * DMODEL);

    // Q/K/V fragment permutes
    permQ_kernel<<<dim3(4, 8, BATCH * NHEAD), 256>>>();
    permKV_kernel<<<dim3(32, BATCH * NHEAD), 256>>>();

    // Flash attention (tensor cores)
    flash_mma<<<dim3(S_LEN / 256, NHEAD, BATCH), 256, FLASH_SMEM>>>(mask);

    // Output projection
    permA_kernel<<<MTOT * DMODEL / 4 / 256, 256>>>(attnL, aperm);
    mma_gemm<2><<<dim3(DMODEL / 128, MTOT / 128), 256, 2 * STAGE_BYTES>>>(
        aperm, boutP, bout, out, DMODEL);
}